// round 12
// baseline (speedup 1.0000x reference)
#include <cuda_runtime.h>
#include <cstdint>

// Inverse 2D Haar wavelet (synthesis), fixed shapes:
//   in : (B=32, C4=256, H=64, W=64) f32   (C4 = C*4: cA,cH,cV,cD per channel)
//   out: (B=32, C=64, 128, 128) f32
//
// Persistent single-wave kernel (592 CTAs = 148 SMs x 4) with a grid-stride
// loop over row-tasks and software prefetch: each warp issues the NEXT
// iteration's 4 subband loads before storing the current iteration, so the
// DRAM read stream never drains at CTA boundaries (kills the ~13 wave
// transitions of the non-persistent version).
//
// Access pattern per task (proven best, R8):
//   lane i loads input cols [2i,2i+2) per subband (float2 via __ldcg)
//   lane i stores output cols [4i,4i+4) of rows 2h, 2h+1 (float4, 512B/warp)

#define IWT_H 64
#define IWT_W 64
#define PLANE_IN  (IWT_H * IWT_W)          // 4096
#define PLANE_OUT (4 * IWT_H * IWT_W)      // 16384
#define N_TASKS   (2048 * 64)              // (B*C) rows = 131072
#define GRID_BLKS 592                      // 148 SMs * 4 CTAs
#define BLK       512

__device__ __forceinline__ void load_task(
    const float* __restrict__ x, int task, int lane,
    float2& a, float2& hh, float2& v, float2& d)
{
    int h  = task & 63;
    int bc = task >> 6;
    const float2* base = (const float2*)(x + (size_t)bc * 4 * PLANE_IN + h * IWT_W + 2 * lane);
    a  = __ldcg(base);
    hh = __ldcg(base + PLANE_IN / 2);
    v  = __ldcg(base + 2 * PLANE_IN / 2);
    d  = __ldcg(base + 3 * PLANE_IN / 2);
}

__device__ __forceinline__ void store_task(
    float* __restrict__ out, int task, int lane,
    float2 a, float2 hh, float2 v, float2 d)
{
    int h  = task & 63;
    int bc = task >> 6;

    float4 r0, r1;
    {
        float ai = a.x, hi = hh.x, vi = v.x, di = d.x;
        r0.x = (ai + hi + vi + di) * 0.5f;
        r0.y = (ai + hi - vi - di) * 0.5f;
        r1.x = (ai - hi + vi - di) * 0.5f;
        r1.y = (ai - hi - vi + di) * 0.5f;
    }
    {
        float ai = a.y, hi = hh.y, vi = v.y, di = d.y;
        r0.z = (ai + hi + vi + di) * 0.5f;
        r0.w = (ai + hi - vi - di) * 0.5f;
        r1.z = (ai - hi + vi - di) * 0.5f;
        r1.w = (ai - hi - vi + di) * 0.5f;
    }

    float* o = out + (size_t)bc * PLANE_OUT + (2 * h) * (2 * IWT_W) + 4 * lane;
    *(float4*)(o)              = r0;   // row 2h
    *(float4*)(o + 2 * IWT_W)  = r1;   // row 2h+1
}

__global__ void __launch_bounds__(BLK, 4) iwt_kernel(
    const float* __restrict__ x, float* __restrict__ out)
{
    int lane = threadIdx.x & 31;
    int w = (blockIdx.x * BLK + threadIdx.x) >> 5;      // global warp id
    const int total_warps = GRID_BLKS * (BLK / 32);     // 9472

    int task = w;
    if (task >= N_TASKS) return;

    float2 a0, h0, v0, d0;
    load_task(x, task, lane, a0, h0, v0, d0);

    for (;;) {
        int next = task + total_warps;
        float2 a1, h1, v1, d1;
        bool has_next = (next < N_TASKS);
        if (has_next)
            load_task(x, next, lane, a1, h1, v1, d1);   // prefetch next iter

        store_task(out, task, lane, a0, h0, v0, d0);

        if (!has_next) break;
        a0 = a1; h0 = h1; v0 = v1; d0 = d1;
        task = next;
    }
}

extern "C" void kernel_launch(void* const* d_in, const int* in_sizes, int n_in,
                              void* d_out, int out_size) {
    const float* x = (const float*)d_in[0];
    float* out = (float*)d_out;
    iwt_kernel<<<GRID_BLKS, BLK>>>(x, out);
}

// round 13
// speedup vs baseline: 1.1533x; 1.1533x over previous
#include <cuda_runtime.h>
#include <cstdint>

// Inverse 2D Haar wavelet (synthesis), fixed shapes:
//   in : (B=32, C4=256, H=64, W=64) f32   (C4 = C*4: cA,cH,cV,cD per channel)
//   out: (B=32, C=64, 128, 128) f32
//
// FINAL — best measured config (kernel 35.42us, DRAM 76.1%, bench 43.49us;
// reproduced 35.4-35.6us across three runs):
//
// Warp-per-input-row mapping:
//   lane i loads input cols [2i,2i+2) per subband (float2, 256B/warp/subband,
//     4 front-batched LDG.64 -> MLP 4)
//   lane i stores output cols [4i,4i+4) of rows 2h and 2h+1 (float4 each,
//     512B fully contiguous per STG.128 -> full-sector store wavefronts)
//   loads via __ldcg: input is single-use, skip the L1 fill.
//
// Floor rationale (R3-R12 evidence): 268MB/pass compulsory traffic; ~22%
// capacity-bound L2 absorption under fixed-order graph replay (persisting
// carveout forbidden by harness rules); ~75% of DRAM spec is the mixed R/W
// stream ceiling. Neutral/negative: 4-row tiles, evict_last/evict_first
// policies, .cs stores, v8.b32 stores, persistent grid + prefetch.

#define IWT_H 64
#define IWT_W 64
#define PLANE_IN  (IWT_H * IWT_W)          // 4096
#define PLANE_OUT (4 * IWT_H * IWT_W)      // 16384

__global__ void __launch_bounds__(512) iwt_kernel(
    const float* __restrict__ x, float* __restrict__ out)
{
    int t = blockIdx.x * blockDim.x + threadIdx.x;
    int lane = t & 31;
    int w = t >> 5;          // warp index = (bc, h)
    int h = w & 63;
    int bc = w >> 6;         // 0 .. B*C-1 (2048)

    const float2* base = (const float2*)(x + (size_t)bc * 4 * PLANE_IN + h * IWT_W + 2 * lane);
    float2 a  = __ldcg(base);
    float2 hh = __ldcg(base + PLANE_IN / 2);
    float2 v  = __ldcg(base + 2 * PLANE_IN / 2);
    float2 d  = __ldcg(base + 3 * PLANE_IN / 2);

    float4 r0, r1;
    {
        float ai = a.x, hi = hh.x, vi = v.x, di = d.x;
        r0.x = (ai + hi + vi + di) * 0.5f;
        r0.y = (ai + hi - vi - di) * 0.5f;
        r1.x = (ai - hi + vi - di) * 0.5f;
        r1.y = (ai - hi - vi + di) * 0.5f;
    }
    {
        float ai = a.y, hi = hh.y, vi = v.y, di = d.y;
        r0.z = (ai + hi + vi + di) * 0.5f;
        r0.w = (ai + hi - vi - di) * 0.5f;
        r1.z = (ai - hi + vi - di) * 0.5f;
        r1.w = (ai - hi - vi + di) * 0.5f;
    }

    float* o = out + (size_t)bc * PLANE_OUT + (2 * h) * (2 * IWT_W) + 4 * lane;
    *(float4*)(o)              = r0;   // row 2h
    *(float4*)(o + 2 * IWT_W)  = r1;   // row 2h+1
}

extern "C" void kernel_launch(void* const* d_in, const int* in_sizes, int n_in,
                              void* d_out, int out_size) {
    const float* x = (const float*)d_in[0];
    float* out = (float*)d_out;

    int total = in_sizes[0];            // 33,554,432 elems
    int threads_total = total / 8;      // 8 elems per thread

    int threads = 512;
    int blocks = threads_total / threads;   // 8192
    iwt_kernel<<<blocks, threads>>>(x, out);
}

// round 14
// speedup vs baseline: 1.1702x; 1.0146x over previous
#include <cuda_runtime.h>
#include <cstdint>

// Inverse 2D Haar wavelet (synthesis), fixed shapes:
//   in : (B=32, C4=256, H=64, W=64) f32   (C4 = C*4: cA,cH,cV,cD per channel)
//   out: (B=32, C=64, 128, 128) f32
//
// FINAL — best measured config (kernel 35.42us / bench 43.49us best;
// reproduced 35.4-35.9us across four independent runs, DRAM 74-76%):
//
// Warp-per-input-row mapping:
//   lane i loads input cols [2i,2i+2) per subband (float2, 256B/warp/subband,
//     4 front-batched LDG.64 -> MLP 4)
//   lane i stores output cols [4i,4i+4) of rows 2h and 2h+1 (float4 each,
//     512B fully contiguous per STG.128 -> full-sector store wavefronts)
//   loads via __ldcg: input is single-use, skip the L1 fill.
//
// Floor evidence (R1-R13): 268MB/pass compulsory traffic; ~22% capacity-bound
// L2 absorption under fixed-order graph replay (persisting carveout forbidden
// by harness device-limit rules); ~75% of DRAM spec = mixed R/W stream
// ceiling. Measured neutral or negative: 4-row tiles, evict_last/evict_first
// policy descriptors, .cs streaming stores, v8.b32 stores, persistent grid
// with software prefetch. Compute/issue pipes all have 4-5x headroom.

#define IWT_H 64
#define IWT_W 64
#define PLANE_IN  (IWT_H * IWT_W)          // 4096
#define PLANE_OUT (4 * IWT_H * IWT_W)      // 16384

__global__ void __launch_bounds__(512) iwt_kernel(
    const float* __restrict__ x, float* __restrict__ out)
{
    int t = blockIdx.x * blockDim.x + threadIdx.x;
    int lane = t & 31;
    int w = t >> 5;          // warp index = (bc, h)
    int h = w & 63;
    int bc = w >> 6;         // 0 .. B*C-1 (2048)

    const float2* base = (const float2*)(x + (size_t)bc * 4 * PLANE_IN + h * IWT_W + 2 * lane);
    float2 a  = __ldcg(base);
    float2 hh = __ldcg(base + PLANE_IN / 2);
    float2 v  = __ldcg(base + 2 * PLANE_IN / 2);
    float2 d  = __ldcg(base + 3 * PLANE_IN / 2);

    float4 r0, r1;
    {
        float ai = a.x, hi = hh.x, vi = v.x, di = d.x;
        r0.x = (ai + hi + vi + di) * 0.5f;
        r0.y = (ai + hi - vi - di) * 0.5f;
        r1.x = (ai - hi + vi - di) * 0.5f;
        r1.y = (ai - hi - vi + di) * 0.5f;
    }
    {
        float ai = a.y, hi = hh.y, vi = v.y, di = d.y;
        r0.z = (ai + hi + vi + di) * 0.5f;
        r0.w = (ai + hi - vi - di) * 0.5f;
        r1.z = (ai - hi + vi - di) * 0.5f;
        r1.w = (ai - hi - vi + di) * 0.5f;
    }

    float* o = out + (size_t)bc * PLANE_OUT + (2 * h) * (2 * IWT_W) + 4 * lane;
    *(float4*)(o)              = r0;   // row 2h
    *(float4*)(o + 2 * IWT_W)  = r1;   // row 2h+1
}

extern "C" void kernel_launch(void* const* d_in, const int* in_sizes, int n_in,
                              void* d_out, int out_size) {
    const float* x = (const float*)d_in[0];
    float* out = (float*)d_out;

    int total = in_sizes[0];            // 33,554,432 elems
    int threads_total = total / 8;      // 8 elems per thread

    int threads = 512;
    int blocks = threads_total / threads;   // 8192
    iwt_kernel<<<blocks, threads>>>(x, out);
}